// round 8
// baseline (speedup 1.0000x reference)
#include <cuda_runtime.h>
#include <math.h>

#define B_  8
#define T_  2048
#define D_  512

#define BM 128
#define BN 128
#define BK 16
#define NT 256
#define PAD 4   // shared row padding (keeps 16B alignment: (128+4)*4 = 528 bytes)

// Scratch (allocation-free rule: __device__ globals)
__device__ float g_QP[B_ * T_ * D_];
__device__ float g_KP[B_ * T_ * D_];
__device__ float g_VP[B_ * T_ * D_];
__device__ float g_S [(size_t)B_ * T_ * T_];

// ---------------------------------------------------------------------------
// Projection: C[m,n] = sum_k X[m,k] * W[n,k] + bias[n]
// M = B*T = 16384, N = K = 512. NT gemm (both operands K-contiguous).
// which: 0 -> g_QP, 1 -> g_KP, 2 -> g_VP
// ---------------------------------------------------------------------------
__global__ __launch_bounds__(NT) void proj_kernel(
    const float* __restrict__ X, const float* __restrict__ W,
    const float* __restrict__ bias, int which)
{
    const int K = D_, N = D_;
    float* C = (which == 0) ? g_QP : (which == 1) ? g_KP : g_VP;

    __shared__ float As[BK][BM + PAD];
    __shared__ float Bs[BK][BN + PAD];

    const int tid = threadIdx.x;
    const int bm  = blockIdx.x * BM;
    const int bn  = blockIdx.y * BN;
    const int tx  = tid & 15;
    const int ty  = tid >> 4;

    float acc[8][8];
#pragma unroll
    for (int i = 0; i < 8; i++)
#pragma unroll
        for (int j = 0; j < 8; j++) acc[i][j] = 0.f;

    const float* Ag = X + (size_t)bm * K;
    const float* Bg = W + (size_t)bn * K;

    for (int k0 = 0; k0 < K; k0 += BK) {
#pragma unroll
        for (int i = 0; i < 2; i++) {
            int idx = tid + i * NT;
            int r = idx >> 2;
            int c = (idx & 3) * 4;
            float4 a = *(const float4*)(Ag + (size_t)r * K + k0 + c);
            As[c + 0][r] = a.x; As[c + 1][r] = a.y;
            As[c + 2][r] = a.z; As[c + 3][r] = a.w;
            float4 b = *(const float4*)(Bg + (size_t)r * K + k0 + c);
            Bs[c + 0][r] = b.x; Bs[c + 1][r] = b.y;
            Bs[c + 2][r] = b.z; Bs[c + 3][r] = b.w;
        }
        __syncthreads();
#pragma unroll
        for (int kk = 0; kk < BK; kk++) {
            float4 a0 = *(const float4*)&As[kk][ty * 4];
            float4 a1 = *(const float4*)&As[kk][64 + ty * 4];
            float4 b0 = *(const float4*)&Bs[kk][tx * 4];
            float4 b1 = *(const float4*)&Bs[kk][64 + tx * 4];
            float ra[8] = {a0.x, a0.y, a0.z, a0.w, a1.x, a1.y, a1.z, a1.w};
            float rb[8] = {b0.x, b0.y, b0.z, b0.w, b1.x, b1.y, b1.z, b1.w};
#pragma unroll
            for (int i = 0; i < 8; i++)
#pragma unroll
                for (int j = 0; j < 8; j++)
                    acc[i][j] = fmaf(ra[i], rb[j], acc[i][j]);
        }
        __syncthreads();
    }

#pragma unroll
    for (int ih = 0; ih < 2; ih++) {
#pragma unroll
        for (int ii = 0; ii < 4; ii++) {
            int m = bm + ih * 64 + ty * 4 + ii;
            int ai = ih * 4 + ii;
#pragma unroll
            for (int jh = 0; jh < 2; jh++) {
                int n = bn + jh * 64 + tx * 4;
                float4 bz = *(const float4*)(bias + n);
                float4 o;
                o.x = acc[ai][jh * 4 + 0] + bz.x;
                o.y = acc[ai][jh * 4 + 1] + bz.y;
                o.z = acc[ai][jh * 4 + 2] + bz.z;
                o.w = acc[ai][jh * 4 + 3] + bz.w;
                *(float4*)(C + (size_t)m * N + n) = o;
            }
        }
    }
}

// ---------------------------------------------------------------------------
// Scores: S[b,m,n] = (sum_k QP[b,m,k] * KP[b,n,k]) * scale * mask[b,m,n]
// Per-batch NT gemm, M = N = T_, K = D_.
// ---------------------------------------------------------------------------
__global__ __launch_bounds__(NT) void score_kernel(
    const float* __restrict__ mask)
{
    const int K = D_, N = T_;
    const float scale = 0.04419417382415922f;  // 1/sqrt(512)

    const int b = blockIdx.z;
    const float* Ag = g_QP + (size_t)b * T_ * D_ + (size_t)blockIdx.x * BM * K;
    const float* Bg = g_KP + (size_t)b * T_ * D_ + (size_t)blockIdx.y * BN * K;
    const float* Mg = mask + (size_t)b * T_ * T_;
    float*       Cg = g_S  + (size_t)b * T_ * T_;

    __shared__ float As[BK][BM + PAD];
    __shared__ float Bs[BK][BN + PAD];

    const int tid = threadIdx.x;
    const int tx  = tid & 15;
    const int ty  = tid >> 4;

    float acc[8][8];
#pragma unroll
    for (int i = 0; i < 8; i++)
#pragma unroll
        for (int j = 0; j < 8; j++) acc[i][j] = 0.f;

    for (int k0 = 0; k0 < K; k0 += BK) {
#pragma unroll
        for (int i = 0; i < 2; i++) {
            int idx = tid + i * NT;
            int r = idx >> 2;
            int c = (idx & 3) * 4;
            float4 a = *(const float4*)(Ag + (size_t)r * K + k0 + c);
            As[c + 0][r] = a.x; As[c + 1][r] = a.y;
            As[c + 2][r] = a.z; As[c + 3][r] = a.w;
            float4 bv = *(const float4*)(Bg + (size_t)r * K + k0 + c);
            Bs[c + 0][r] = bv.x; Bs[c + 1][r] = bv.y;
            Bs[c + 2][r] = bv.z; Bs[c + 3][r] = bv.w;
        }
        __syncthreads();
#pragma unroll
        for (int kk = 0; kk < BK; kk++) {
            float4 a0 = *(const float4*)&As[kk][ty * 4];
            float4 a1 = *(const float4*)&As[kk][64 + ty * 4];
            float4 b0 = *(const float4*)&Bs[kk][tx * 4];
            float4 b1 = *(const float4*)&Bs[kk][64 + tx * 4];
            float ra[8] = {a0.x, a0.y, a0.z, a0.w, a1.x, a1.y, a1.z, a1.w};
            float rb[8] = {b0.x, b0.y, b0.z, b0.w, b1.x, b1.y, b1.z, b1.w};
#pragma unroll
            for (int i = 0; i < 8; i++)
#pragma unroll
                for (int j = 0; j < 8; j++)
                    acc[i][j] = fmaf(ra[i], rb[j], acc[i][j]);
        }
        __syncthreads();
    }

    const int bm = blockIdx.x * BM;
    const int bn = blockIdx.y * BN;
#pragma unroll
    for (int ih = 0; ih < 2; ih++) {
#pragma unroll
        for (int ii = 0; ii < 4; ii++) {
            int m = bm + ih * 64 + ty * 4 + ii;
            int ai = ih * 4 + ii;
#pragma unroll
            for (int jh = 0; jh < 2; jh++) {
                int n = bn + jh * 64 + tx * 4;
                float4 mk = *(const float4*)(Mg + (size_t)m * N + n);
                float4 o;
                o.x = acc[ai][jh * 4 + 0] * scale * mk.x;
                o.y = acc[ai][jh * 4 + 1] * scale * mk.y;
                o.z = acc[ai][jh * 4 + 2] * scale * mk.z;
                o.w = acc[ai][jh * 4 + 3] * scale * mk.w;
                *(float4*)(Cg + (size_t)m * N + n) = o;
            }
        }
    }
}

// ---------------------------------------------------------------------------
// Row softmax over g_S: one CTA per row (B*T rows, T_ cols).
// Each thread holds its 8 values in registers: 1 read + 1 write per element.
// ---------------------------------------------------------------------------
__global__ __launch_bounds__(NT) void softmax_kernel()
{
    float* p = g_S + (size_t)blockIdx.x * T_;
    const int tid = threadIdx.x;

    float4 a = *(const float4*)(p + tid * 4);
    float4 b = *(const float4*)(p + 1024 + tid * 4);

    float m = fmaxf(fmaxf(fmaxf(a.x, a.y), fmaxf(a.z, a.w)),
                    fmaxf(fmaxf(b.x, b.y), fmaxf(b.z, b.w)));

    __shared__ float red[NT];
    red[tid] = m;
    __syncthreads();
#pragma unroll
    for (int s = NT / 2; s > 0; s >>= 1) {
        if (tid < s) red[tid] = fmaxf(red[tid], red[tid + s]);
        __syncthreads();
    }
    float rowmax = red[0];
    __syncthreads();

    a.x = __expf(a.x - rowmax); a.y = __expf(a.y - rowmax);
    a.z = __expf(a.z - rowmax); a.w = __expf(a.w - rowmax);
    b.x = __expf(b.x - rowmax); b.y = __expf(b.y - rowmax);
    b.z = __expf(b.z - rowmax); b.w = __expf(b.w - rowmax);

    float s8 = (a.x + a.y) + (a.z + a.w) + (b.x + b.y) + (b.z + b.w);
    red[tid] = s8;
    __syncthreads();
#pragma unroll
    for (int s = NT / 2; s > 0; s >>= 1) {
        if (tid < s) red[tid] += red[tid + s];
        __syncthreads();
    }
    float inv = 1.0f / red[0];

    a.x *= inv; a.y *= inv; a.z *= inv; a.w *= inv;
    b.x *= inv; b.y *= inv; b.z *= inv; b.w *= inv;
    *(float4*)(p + tid * 4) = a;
    *(float4*)(p + 1024 + tid * 4) = b;
}

// ---------------------------------------------------------------------------
// Output: O[b,m,n] = sum_k P[b,m,k] * VP[b,k,n]
// Per-batch NN gemm, M = T_, N = D_, K = T_. P K-contiguous, V N-contiguous.
// ---------------------------------------------------------------------------
__global__ __launch_bounds__(NT) void pv_kernel(float* __restrict__ out)
{
    const int K = T_, N = D_;

    const int b = blockIdx.z;
    const float* Ag = g_S  + (size_t)b * T_ * T_ + (size_t)blockIdx.x * BM * K;
    const float* Bg = g_VP + (size_t)b * T_ * D_;
    float*       Cg = out  + (size_t)b * T_ * D_;

    __shared__ float As[BK][BM + PAD];
    __shared__ float Bs[BK][BN + PAD];

    const int tid = threadIdx.x;
    const int bn  = blockIdx.y * BN;
    const int tx  = tid & 15;
    const int ty  = tid >> 4;

    float acc[8][8];
#pragma unroll
    for (int i = 0; i < 8; i++)
#pragma unroll
        for (int j = 0; j < 8; j++) acc[i][j] = 0.f;

    for (int k0 = 0; k0 < K; k0 += BK) {
        // A tile: 128 rows x 16 k (K-contiguous), transposed into As
#pragma unroll
        for (int i = 0; i < 2; i++) {
            int idx = tid + i * NT;
            int r = idx >> 2;
            int c = (idx & 3) * 4;
            float4 a = *(const float4*)(Ag + (size_t)r * K + k0 + c);
            As[c + 0][r] = a.x; As[c + 1][r] = a.y;
            As[c + 2][r] = a.z; As[c + 3][r] = a.w;
        }
        // B tile: 16 k-rows x 128 n (N-contiguous), direct
#pragma unroll
        for (int i = 0; i < 2; i++) {
            int idx = tid + i * NT;
            int kr = idx >> 5;
            int c4 = idx & 31;
            float4 vv = *(const float4*)(Bg + (size_t)(k0 + kr) * N + bn + c4 * 4);
            *(float4*)&Bs[kr][c4 * 4] = vv;
        }
        __syncthreads();
#pragma unroll
        for (int kk = 0; kk < BK; kk++) {
            float4 a0 = *(const float4*)&As[kk][ty * 4];
            float4 a1 = *(const float4*)&As[kk][64 + ty * 4];
            float4 b0 = *(const float4*)&Bs[kk][tx * 4];
            float4 b1 = *(const float4*)&Bs[kk][64 + tx * 4];
            float ra[8] = {a0.x, a0.y, a0.z, a0.w, a1.x, a1.y, a1.z, a1.w};
            float rb[8] = {b0.x, b0.y, b0.z, b0.w, b1.x, b1.y, b1.z, b1.w};
#pragma unroll
            for (int i = 0; i < 8; i++)
#pragma unroll
                for (int j = 0; j < 8; j++)
                    acc[i][j] = fmaf(ra[i], rb[j], acc[i][j]);
        }
        __syncthreads();
    }

    const int bm = blockIdx.x * BM;
#pragma unroll
    for (int ih = 0; ih < 2; ih++) {
#pragma unroll
        for (int ii = 0; ii < 4; ii++) {
            int m = bm + ih * 64 + ty * 4 + ii;
            int ai = ih * 4 + ii;
#pragma unroll
            for (int jh = 0; jh < 2; jh++) {
                int n = bn + jh * 64 + tx * 4;
                float4 o;
                o.x = acc[ai][jh * 4 + 0];
                o.y = acc[ai][jh * 4 + 1];
                o.z = acc[ai][jh * 4 + 2];
                o.w = acc[ai][jh * 4 + 3];
                *(float4*)(Cg + (size_t)m * N + n) = o;
            }
        }
    }
}

// ---------------------------------------------------------------------------
// Launch
// ---------------------------------------------------------------------------
extern "C" void kernel_launch(void* const* d_in, const int* in_sizes, int n_in,
                              void* d_out, int out_size)
{
    const float* q    = (const float*)d_in[0];
    const float* k    = (const float*)d_in[1];
    const float* v    = (const float*)d_in[2];
    const float* Wq   = (const float*)d_in[3];
    const float* bq   = (const float*)d_in[4];
    const float* Wk   = (const float*)d_in[5];
    const float* bk   = (const float*)d_in[6];
    const float* Wv   = (const float*)d_in[7];
    const float* bv   = (const float*)d_in[8];
    const float* mask = (const float*)d_in[9];
    float* out = (float*)d_out;

    // 1) Projections: M = B*T = 16384, N = 512
    dim3 gp((B_ * T_) / BM, D_ / BN);
    proj_kernel<<<gp, NT>>>(q, Wq, bq, 0);
    proj_kernel<<<gp, NT>>>(k, Wk, bk, 1);
    proj_kernel<<<gp, NT>>>(v, Wv, bv, 2);

    // 2) Scores (scale + mask fused in epilogue)
    dim3 gs(T_ / BM, T_ / BN, B_);
    score_kernel<<<gs, NT>>>(mask);

    // 3) Row softmax
    softmax_kernel<<<B_ * T_, NT>>>();

    // 4) O = P @ V
    dim3 go(T_ / BM, D_ / BN, B_);
    pv_kernel<<<go, NT>>>(out);
}

// round 9
// speedup vs baseline: 1.0010x; 1.0010x over previous
#include <cuda_runtime.h>
#include <math.h>

#define B_  8
#define T_  2048
#define D_  512

#define BM 128
#define BN 128
#define BK 16
#define NT 256
#define PAD 4   // shared row padding (keeps 16B alignment: (128+4)*4 = 528 bytes)

// Scratch (allocation-free rule: __device__ globals)
__device__ float g_QP[B_ * T_ * D_];
__device__ float g_KP[B_ * T_ * D_];
__device__ float g_VP[B_ * T_ * D_];
__device__ float g_S [(size_t)B_ * T_ * T_];

// ---------------------------------------------------------------------------
// Projection: C[m,n] = sum_k X[m,k] * W[n,k] + bias[n]
// M = B*T = 16384, N = K = 512. NT gemm (both operands K-contiguous).
// which: 0 -> g_QP, 1 -> g_KP, 2 -> g_VP
// ---------------------------------------------------------------------------
__global__ __launch_bounds__(NT) void proj_kernel(
    const float* __restrict__ X, const float* __restrict__ W,
    const float* __restrict__ bias, int which)
{
    const int K = D_, N = D_;
    float* C = (which == 0) ? g_QP : (which == 1) ? g_KP : g_VP;

    __shared__ float As[BK][BM + PAD];
    __shared__ float Bs[BK][BN + PAD];

    const int tid = threadIdx.x;
    const int bm  = blockIdx.x * BM;
    const int bn  = blockIdx.y * BN;
    const int tx  = tid & 15;
    const int ty  = tid >> 4;

    float acc[8][8];
#pragma unroll
    for (int i = 0; i < 8; i++)
#pragma unroll
        for (int j = 0; j < 8; j++) acc[i][j] = 0.f;

    const float* Ag = X + (size_t)bm * K;
    const float* Bg = W + (size_t)bn * K;

    for (int k0 = 0; k0 < K; k0 += BK) {
#pragma unroll
        for (int i = 0; i < 2; i++) {
            int idx = tid + i * NT;
            int r = idx >> 2;
            int c = (idx & 3) * 4;
            float4 a = *(const float4*)(Ag + (size_t)r * K + k0 + c);
            As[c + 0][r] = a.x; As[c + 1][r] = a.y;
            As[c + 2][r] = a.z; As[c + 3][r] = a.w;
            float4 b = *(const float4*)(Bg + (size_t)r * K + k0 + c);
            Bs[c + 0][r] = b.x; Bs[c + 1][r] = b.y;
            Bs[c + 2][r] = b.z; Bs[c + 3][r] = b.w;
        }
        __syncthreads();
#pragma unroll
        for (int kk = 0; kk < BK; kk++) {
            float4 a0 = *(const float4*)&As[kk][ty * 4];
            float4 a1 = *(const float4*)&As[kk][64 + ty * 4];
            float4 b0 = *(const float4*)&Bs[kk][tx * 4];
            float4 b1 = *(const float4*)&Bs[kk][64 + tx * 4];
            float ra[8] = {a0.x, a0.y, a0.z, a0.w, a1.x, a1.y, a1.z, a1.w};
            float rb[8] = {b0.x, b0.y, b0.z, b0.w, b1.x, b1.y, b1.z, b1.w};
#pragma unroll
            for (int i = 0; i < 8; i++)
#pragma unroll
                for (int j = 0; j < 8; j++)
                    acc[i][j] = fmaf(ra[i], rb[j], acc[i][j]);
        }
        __syncthreads();
    }

#pragma unroll
    for (int ih = 0; ih < 2; ih++) {
#pragma unroll
        for (int ii = 0; ii < 4; ii++) {
            int m = bm + ih * 64 + ty * 4 + ii;
            int ai = ih * 4 + ii;
#pragma unroll
            for (int jh = 0; jh < 2; jh++) {
                int n = bn + jh * 64 + tx * 4;
                float4 bz = *(const float4*)(bias + n);
                float4 o;
                o.x = acc[ai][jh * 4 + 0] + bz.x;
                o.y = acc[ai][jh * 4 + 1] + bz.y;
                o.z = acc[ai][jh * 4 + 2] + bz.z;
                o.w = acc[ai][jh * 4 + 3] + bz.w;
                *(float4*)(C + (size_t)m * N + n) = o;
            }
        }
    }
}

// ---------------------------------------------------------------------------
// Scores: S[b,m,n] = (sum_k QP[b,m,k] * KP[b,n,k]) * scale * mask[b,m,n]
// Per-batch NT gemm, M = N = T_, K = D_.
// ---------------------------------------------------------------------------
__global__ __launch_bounds__(NT) void score_kernel(
    const float* __restrict__ mask)
{
    const int K = D_, N = T_;
    const float scale = 0.04419417382415922f;  // 1/sqrt(512)

    const int b = blockIdx.z;
    const float* Ag = g_QP + (size_t)b * T_ * D_ + (size_t)blockIdx.x * BM * K;
    const float* Bg = g_KP + (size_t)b * T_ * D_ + (size_t)blockIdx.y * BN * K;
    const float* Mg = mask + (size_t)b * T_ * T_;
    float*       Cg = g_S  + (size_t)b * T_ * T_;

    __shared__ float As[BK][BM + PAD];
    __shared__ float Bs[BK][BN + PAD];

    const int tid = threadIdx.x;
    const int tx  = tid & 15;
    const int ty  = tid >> 4;

    float acc[8][8];
#pragma unroll
    for (int i = 0; i < 8; i++)
#pragma unroll
        for (int j = 0; j < 8; j++) acc[i][j] = 0.f;

    for (int k0 = 0; k0 < K; k0 += BK) {
#pragma unroll
        for (int i = 0; i < 2; i++) {
            int idx = tid + i * NT;
            int r = idx >> 2;
            int c = (idx & 3) * 4;
            float4 a = *(const float4*)(Ag + (size_t)r * K + k0 + c);
            As[c + 0][r] = a.x; As[c + 1][r] = a.y;
            As[c + 2][r] = a.z; As[c + 3][r] = a.w;
            float4 bv = *(const float4*)(Bg + (size_t)r * K + k0 + c);
            Bs[c + 0][r] = bv.x; Bs[c + 1][r] = bv.y;
            Bs[c + 2][r] = bv.z; Bs[c + 3][r] = bv.w;
        }
        __syncthreads();
#pragma unroll
        for (int kk = 0; kk < BK; kk++) {
            float4 a0 = *(const float4*)&As[kk][ty * 4];
            float4 a1 = *(const float4*)&As[kk][64 + ty * 4];
            float4 b0 = *(const float4*)&Bs[kk][tx * 4];
            float4 b1 = *(const float4*)&Bs[kk][64 + tx * 4];
            float ra[8] = {a0.x, a0.y, a0.z, a0.w, a1.x, a1.y, a1.z, a1.w};
            float rb[8] = {b0.x, b0.y, b0.z, b0.w, b1.x, b1.y, b1.z, b1.w};
#pragma unroll
            for (int i = 0; i < 8; i++)
#pragma unroll
                for (int j = 0; j < 8; j++)
                    acc[i][j] = fmaf(ra[i], rb[j], acc[i][j]);
        }
        __syncthreads();
    }

    const int bm = blockIdx.x * BM;
    const int bn = blockIdx.y * BN;
#pragma unroll
    for (int ih = 0; ih < 2; ih++) {
#pragma unroll
        for (int ii = 0; ii < 4; ii++) {
            int m = bm + ih * 64 + ty * 4 + ii;
            int ai = ih * 4 + ii;
#pragma unroll
            for (int jh = 0; jh < 2; jh++) {
                int n = bn + jh * 64 + tx * 4;
                float4 mk = *(const float4*)(Mg + (size_t)m * N + n);
                float4 o;
                o.x = acc[ai][jh * 4 + 0] * scale * mk.x;
                o.y = acc[ai][jh * 4 + 1] * scale * mk.y;
                o.z = acc[ai][jh * 4 + 2] * scale * mk.z;
                o.w = acc[ai][jh * 4 + 3] * scale * mk.w;
                *(float4*)(Cg + (size_t)m * N + n) = o;
            }
        }
    }
}

// ---------------------------------------------------------------------------
// Row softmax over g_S: one CTA per row (B*T rows, T_ cols).
// Each thread holds its 8 values in registers: 1 read + 1 write per element.
// ---------------------------------------------------------------------------
__global__ __launch_bounds__(NT) void softmax_kernel()
{
    float* p = g_S + (size_t)blockIdx.x * T_;
    const int tid = threadIdx.x;

    float4 a = *(const float4*)(p + tid * 4);
    float4 b = *(const float4*)(p + 1024 + tid * 4);

    float m = fmaxf(fmaxf(fmaxf(a.x, a.y), fmaxf(a.z, a.w)),
                    fmaxf(fmaxf(b.x, b.y), fmaxf(b.z, b.w)));

    __shared__ float red[NT];
    red[tid] = m;
    __syncthreads();
#pragma unroll
    for (int s = NT / 2; s > 0; s >>= 1) {
        if (tid < s) red[tid] = fmaxf(red[tid], red[tid + s]);
        __syncthreads();
    }
    float rowmax = red[0];
    __syncthreads();

    a.x = __expf(a.x - rowmax); a.y = __expf(a.y - rowmax);
    a.z = __expf(a.z - rowmax); a.w = __expf(a.w - rowmax);
    b.x = __expf(b.x - rowmax); b.y = __expf(b.y - rowmax);
    b.z = __expf(b.z - rowmax); b.w = __expf(b.w - rowmax);

    float s8 = (a.x + a.y) + (a.z + a.w) + (b.x + b.y) + (b.z + b.w);
    red[tid] = s8;
    __syncthreads();
#pragma unroll
    for (int s = NT / 2; s > 0; s >>= 1) {
        if (tid < s) red[tid] += red[tid + s];
        __syncthreads();
    }
    float inv = 1.0f / red[0];

    a.x *= inv; a.y *= inv; a.z *= inv; a.w *= inv;
    b.x *= inv; b.y *= inv; b.z *= inv; b.w *= inv;
    *(float4*)(p + tid * 4) = a;
    *(float4*)(p + 1024 + tid * 4) = b;
}

// ---------------------------------------------------------------------------
// Output: O[b,m,n] = sum_k P[b,m,k] * VP[b,k,n]
// Per-batch NN gemm, M = T_, N = D_, K = T_. P K-contiguous, V N-contiguous.
// ---------------------------------------------------------------------------
__global__ __launch_bounds__(NT) void pv_kernel(float* __restrict__ out)
{
    const int K = T_, N = D_;

    const int b = blockIdx.z;
    const float* Ag = g_S  + (size_t)b * T_ * T_ + (size_t)blockIdx.x * BM * K;
    const float* Bg = g_VP + (size_t)b * T_ * D_;
    float*       Cg = out  + (size_t)b * T_ * D_;

    __shared__ float As[BK][BM + PAD];
    __shared__ float Bs[BK][BN + PAD];

    const int tid = threadIdx.x;
    const int bn  = blockIdx.y * BN;
    const int tx  = tid & 15;
    const int ty  = tid >> 4;

    float acc[8][8];
#pragma unroll
    for (int i = 0; i < 8; i++)
#pragma unroll
        for (int j = 0; j < 8; j++) acc[i][j] = 0.f;

    for (int k0 = 0; k0 < K; k0 += BK) {
        // A tile: 128 rows x 16 k (K-contiguous), transposed into As
#pragma unroll
        for (int i = 0; i < 2; i++) {
            int idx = tid + i * NT;
            int r = idx >> 2;
            int c = (idx & 3) * 4;
            float4 a = *(const float4*)(Ag + (size_t)r * K + k0 + c);
            As[c + 0][r] = a.x; As[c + 1][r] = a.y;
            As[c + 2][r] = a.z; As[c + 3][r] = a.w;
        }
        // B tile: 16 k-rows x 128 n (N-contiguous), direct
#pragma unroll
        for (int i = 0; i < 2; i++) {
            int idx = tid + i * NT;
            int kr = idx >> 5;
            int c4 = idx & 31;
            float4 vv = *(const float4*)(Bg + (size_t)(k0 + kr) * N + bn + c4 * 4);
            *(float4*)&Bs[kr][c4 * 4] = vv;
        }
        __syncthreads();
#pragma unroll
        for (int kk = 0; kk < BK; kk++) {
            float4 a0 = *(const float4*)&As[kk][ty * 4];
            float4 a1 = *(const float4*)&As[kk][64 + ty * 4];
            float4 b0 = *(const float4*)&Bs[kk][tx * 4];
            float4 b1 = *(const float4*)&Bs[kk][64 + tx * 4];
            float ra[8] = {a0.x, a0.y, a0.z, a0.w, a1.x, a1.y, a1.z, a1.w};
            float rb[8] = {b0.x, b0.y, b0.z, b0.w, b1.x, b1.y, b1.z, b1.w};
#pragma unroll
            for (int i = 0; i < 8; i++)
#pragma unroll
                for (int j = 0; j < 8; j++)
                    acc[i][j] = fmaf(ra[i], rb[j], acc[i][j]);
        }
        __syncthreads();
    }

    const int bm = blockIdx.x * BM;
#pragma unroll
    for (int ih = 0; ih < 2; ih++) {
#pragma unroll
        for (int ii = 0; ii < 4; ii++) {
            int m = bm + ih * 64 + ty * 4 + ii;
            int ai = ih * 4 + ii;
#pragma unroll
            for (int jh = 0; jh < 2; jh++) {
                int n = bn + jh * 64 + tx * 4;
                float4 o;
                o.x = acc[ai][jh * 4 + 0];
                o.y = acc[ai][jh * 4 + 1];
                o.z = acc[ai][jh * 4 + 2];
                o.w = acc[ai][jh * 4 + 3];
                *(float4*)(Cg + (size_t)m * N + n) = o;
            }
        }
    }
}

// ---------------------------------------------------------------------------
// Launch
// ---------------------------------------------------------------------------
extern "C" void kernel_launch(void* const* d_in, const int* in_sizes, int n_in,
                              void* d_out, int out_size)
{
    const float* q    = (const float*)d_in[0];
    const float* k    = (const float*)d_in[1];
    const float* v    = (const float*)d_in[2];
    const float* Wq   = (const float*)d_in[3];
    const float* bq   = (const float*)d_in[4];
    const float* Wk   = (const float*)d_in[5];
    const float* bk   = (const float*)d_in[6];
    const float* Wv   = (const float*)d_in[7];
    const float* bv   = (const float*)d_in[8];
    const float* mask = (const float*)d_in[9];
    float* out = (float*)d_out;

    // 1) Projections: M = B*T = 16384, N = 512
    dim3 gp((B_ * T_) / BM, D_ / BN);
    proj_kernel<<<gp, NT>>>(q, Wq, bq, 0);
    proj_kernel<<<gp, NT>>>(k, Wk, bk, 1);
    proj_kernel<<<gp, NT>>>(v, Wv, bv, 2);

    // 2) Scores (scale + mask fused in epilogue)
    dim3 gs(T_ / BM, T_ / BN, B_);
    score_kernel<<<gs, NT>>>(mask);

    // 3) Row softmax
    softmax_kernel<<<B_ * T_, NT>>>();

    // 4) O = P @ V
    dim3 go(T_ / BM, D_ / BN, B_);
    pv_kernel<<<go, NT>>>(out);
}

// round 10
// speedup vs baseline: 1.0022x; 1.0012x over previous
#include <cuda_runtime.h>
#include <math.h>

#define B_  8
#define T_  2048
#define D_  512

#define BM 128
#define BN 128
#define BK 16
#define NT 256
#define PAD 4   // shared row padding (keeps 16B alignment: (128+4)*4 = 528 bytes)

// Scratch (allocation-free rule: __device__ globals)
__device__ float g_QP[B_ * T_ * D_];
__device__ float g_KP[B_ * T_ * D_];
__device__ float g_VP[B_ * T_ * D_];
__device__ float g_S [(size_t)B_ * T_ * T_];

// ---------------------------------------------------------------------------
// Projection: C[m,n] = sum_k X[m,k] * W[n,k] + bias[n]
// M = B*T = 16384, N = K = 512. NT gemm (both operands K-contiguous).
// which: 0 -> g_QP, 1 -> g_KP, 2 -> g_VP
// ---------------------------------------------------------------------------
__global__ __launch_bounds__(NT) void proj_kernel(
    const float* __restrict__ X, const float* __restrict__ W,
    const float* __restrict__ bias, int which)
{
    const int K = D_, N = D_;
    float* C = (which == 0) ? g_QP : (which == 1) ? g_KP : g_VP;

    __shared__ float As[BK][BM + PAD];
    __shared__ float Bs[BK][BN + PAD];

    const int tid = threadIdx.x;
    const int bm  = blockIdx.x * BM;
    const int bn  = blockIdx.y * BN;
    const int tx  = tid & 15;
    const int ty  = tid >> 4;

    float acc[8][8];
#pragma unroll
    for (int i = 0; i < 8; i++)
#pragma unroll
        for (int j = 0; j < 8; j++) acc[i][j] = 0.f;

    const float* Ag = X + (size_t)bm * K;
    const float* Bg = W + (size_t)bn * K;

    for (int k0 = 0; k0 < K; k0 += BK) {
#pragma unroll
        for (int i = 0; i < 2; i++) {
            int idx = tid + i * NT;
            int r = idx >> 2;
            int c = (idx & 3) * 4;
            float4 a = *(const float4*)(Ag + (size_t)r * K + k0 + c);
            As[c + 0][r] = a.x; As[c + 1][r] = a.y;
            As[c + 2][r] = a.z; As[c + 3][r] = a.w;
            float4 b = *(const float4*)(Bg + (size_t)r * K + k0 + c);
            Bs[c + 0][r] = b.x; Bs[c + 1][r] = b.y;
            Bs[c + 2][r] = b.z; Bs[c + 3][r] = b.w;
        }
        __syncthreads();
#pragma unroll
        for (int kk = 0; kk < BK; kk++) {
            float4 a0 = *(const float4*)&As[kk][ty * 4];
            float4 a1 = *(const float4*)&As[kk][64 + ty * 4];
            float4 b0 = *(const float4*)&Bs[kk][tx * 4];
            float4 b1 = *(const float4*)&Bs[kk][64 + tx * 4];
            float ra[8] = {a0.x, a0.y, a0.z, a0.w, a1.x, a1.y, a1.z, a1.w};
            float rb[8] = {b0.x, b0.y, b0.z, b0.w, b1.x, b1.y, b1.z, b1.w};
#pragma unroll
            for (int i = 0; i < 8; i++)
#pragma unroll
                for (int j = 0; j < 8; j++)
                    acc[i][j] = fmaf(ra[i], rb[j], acc[i][j]);
        }
        __syncthreads();
    }

#pragma unroll
    for (int ih = 0; ih < 2; ih++) {
#pragma unroll
        for (int ii = 0; ii < 4; ii++) {
            int m = bm + ih * 64 + ty * 4 + ii;
            int ai = ih * 4 + ii;
#pragma unroll
            for (int jh = 0; jh < 2; jh++) {
                int n = bn + jh * 64 + tx * 4;
                float4 bz = *(const float4*)(bias + n);
                float4 o;
                o.x = acc[ai][jh * 4 + 0] + bz.x;
                o.y = acc[ai][jh * 4 + 1] + bz.y;
                o.z = acc[ai][jh * 4 + 2] + bz.z;
                o.w = acc[ai][jh * 4 + 3] + bz.w;
                *(float4*)(C + (size_t)m * N + n) = o;
            }
        }
    }
}

// ---------------------------------------------------------------------------
// Scores: S[b,m,n] = (sum_k QP[b,m,k] * KP[b,n,k]) * scale * mask[b,m,n]
// Per-batch NT gemm, M = N = T_, K = D_.
// ---------------------------------------------------------------------------
__global__ __launch_bounds__(NT) void score_kernel(
    const float* __restrict__ mask)
{
    const int K = D_, N = T_;
    const float scale = 0.04419417382415922f;  // 1/sqrt(512)

    const int b = blockIdx.z;
    const float* Ag = g_QP + (size_t)b * T_ * D_ + (size_t)blockIdx.x * BM * K;
    const float* Bg = g_KP + (size_t)b * T_ * D_ + (size_t)blockIdx.y * BN * K;
    const float* Mg = mask + (size_t)b * T_ * T_;
    float*       Cg = g_S  + (size_t)b * T_ * T_;

    __shared__ float As[BK][BM + PAD];
    __shared__ float Bs[BK][BN + PAD];

    const int tid = threadIdx.x;
    const int tx  = tid & 15;
    const int ty  = tid >> 4;

    float acc[8][8];
#pragma unroll
    for (int i = 0; i < 8; i++)
#pragma unroll
        for (int j = 0; j < 8; j++) acc[i][j] = 0.f;

    for (int k0 = 0; k0 < K; k0 += BK) {
#pragma unroll
        for (int i = 0; i < 2; i++) {
            int idx = tid + i * NT;
            int r = idx >> 2;
            int c = (idx & 3) * 4;
            float4 a = *(const float4*)(Ag + (size_t)r * K + k0 + c);
            As[c + 0][r] = a.x; As[c + 1][r] = a.y;
            As[c + 2][r] = a.z; As[c + 3][r] = a.w;
            float4 bv = *(const float4*)(Bg + (size_t)r * K + k0 + c);
            Bs[c + 0][r] = bv.x; Bs[c + 1][r] = bv.y;
            Bs[c + 2][r] = bv.z; Bs[c + 3][r] = bv.w;
        }
        __syncthreads();
#pragma unroll
        for (int kk = 0; kk < BK; kk++) {
            float4 a0 = *(const float4*)&As[kk][ty * 4];
            float4 a1 = *(const float4*)&As[kk][64 + ty * 4];
            float4 b0 = *(const float4*)&Bs[kk][tx * 4];
            float4 b1 = *(const float4*)&Bs[kk][64 + tx * 4];
            float ra[8] = {a0.x, a0.y, a0.z, a0.w, a1.x, a1.y, a1.z, a1.w};
            float rb[8] = {b0.x, b0.y, b0.z, b0.w, b1.x, b1.y, b1.z, b1.w};
#pragma unroll
            for (int i = 0; i < 8; i++)
#pragma unroll
                for (int j = 0; j < 8; j++)
                    acc[i][j] = fmaf(ra[i], rb[j], acc[i][j]);
        }
        __syncthreads();
    }

    const int bm = blockIdx.x * BM;
    const int bn = blockIdx.y * BN;
#pragma unroll
    for (int ih = 0; ih < 2; ih++) {
#pragma unroll
        for (int ii = 0; ii < 4; ii++) {
            int m = bm + ih * 64 + ty * 4 + ii;
            int ai = ih * 4 + ii;
#pragma unroll
            for (int jh = 0; jh < 2; jh++) {
                int n = bn + jh * 64 + tx * 4;
                float4 mk = *(const float4*)(Mg + (size_t)m * N + n);
                float4 o;
                o.x = acc[ai][jh * 4 + 0] * scale * mk.x;
                o.y = acc[ai][jh * 4 + 1] * scale * mk.y;
                o.z = acc[ai][jh * 4 + 2] * scale * mk.z;
                o.w = acc[ai][jh * 4 + 3] * scale * mk.w;
                *(float4*)(Cg + (size_t)m * N + n) = o;
            }
        }
    }
}

// ---------------------------------------------------------------------------
// Row softmax over g_S: one CTA per row (B*T rows, T_ cols).
// Each thread holds its 8 values in registers: 1 read + 1 write per element.
// ---------------------------------------------------------------------------
__global__ __launch_bounds__(NT) void softmax_kernel()
{
    float* p = g_S + (size_t)blockIdx.x * T_;
    const int tid = threadIdx.x;

    float4 a = *(const float4*)(p + tid * 4);
    float4 b = *(const float4*)(p + 1024 + tid * 4);

    float m = fmaxf(fmaxf(fmaxf(a.x, a.y), fmaxf(a.z, a.w)),
                    fmaxf(fmaxf(b.x, b.y), fmaxf(b.z, b.w)));

    __shared__ float red[NT];
    red[tid] = m;
    __syncthreads();
#pragma unroll
    for (int s = NT / 2; s > 0; s >>= 1) {
        if (tid < s) red[tid] = fmaxf(red[tid], red[tid + s]);
        __syncthreads();
    }
    float rowmax = red[0];
    __syncthreads();

    a.x = __expf(a.x - rowmax); a.y = __expf(a.y - rowmax);
    a.z = __expf(a.z - rowmax); a.w = __expf(a.w - rowmax);
    b.x = __expf(b.x - rowmax); b.y = __expf(b.y - rowmax);
    b.z = __expf(b.z - rowmax); b.w = __expf(b.w - rowmax);

    float s8 = (a.x + a.y) + (a.z + a.w) + (b.x + b.y) + (b.z + b.w);
    red[tid] = s8;
    __syncthreads();
#pragma unroll
    for (int s = NT / 2; s > 0; s >>= 1) {
        if (tid < s) red[tid] += red[tid + s];
        __syncthreads();
    }
    float inv = 1.0f / red[0];

    a.x *= inv; a.y *= inv; a.z *= inv; a.w *= inv;
    b.x *= inv; b.y *= inv; b.z *= inv; b.w *= inv;
    *(float4*)(p + tid * 4) = a;
    *(float4*)(p + 1024 + tid * 4) = b;
}

// ---------------------------------------------------------------------------
// Output: O[b,m,n] = sum_k P[b,m,k] * VP[b,k,n]
// Per-batch NN gemm, M = T_, N = D_, K = T_. P K-contiguous, V N-contiguous.
// ---------------------------------------------------------------------------
__global__ __launch_bounds__(NT) void pv_kernel(float* __restrict__ out)
{
    const int K = T_, N = D_;

    const int b = blockIdx.z;
    const float* Ag = g_S  + (size_t)b * T_ * T_ + (size_t)blockIdx.x * BM * K;
    const float* Bg = g_VP + (size_t)b * T_ * D_;
    float*       Cg = out  + (size_t)b * T_ * D_;

    __shared__ float As[BK][BM + PAD];
    __shared__ float Bs[BK][BN + PAD];

    const int tid = threadIdx.x;
    const int bn  = blockIdx.y * BN;
    const int tx  = tid & 15;
    const int ty  = tid >> 4;

    float acc[8][8];
#pragma unroll
    for (int i = 0; i < 8; i++)
#pragma unroll
        for (int j = 0; j < 8; j++) acc[i][j] = 0.f;

    for (int k0 = 0; k0 < K; k0 += BK) {
        // A tile: 128 rows x 16 k (K-contiguous), transposed into As
#pragma unroll
        for (int i = 0; i < 2; i++) {
            int idx = tid + i * NT;
            int r = idx >> 2;
            int c = (idx & 3) * 4;
            float4 a = *(const float4*)(Ag + (size_t)r * K + k0 + c);
            As[c + 0][r] = a.x; As[c + 1][r] = a.y;
            As[c + 2][r] = a.z; As[c + 3][r] = a.w;
        }
        // B tile: 16 k-rows x 128 n (N-contiguous), direct
#pragma unroll
        for (int i = 0; i < 2; i++) {
            int idx = tid + i * NT;
            int kr = idx >> 5;
            int c4 = idx & 31;
            float4 vv = *(const float4*)(Bg + (size_t)(k0 + kr) * N + bn + c4 * 4);
            *(float4*)&Bs[kr][c4 * 4] = vv;
        }
        __syncthreads();
#pragma unroll
        for (int kk = 0; kk < BK; kk++) {
            float4 a0 = *(const float4*)&As[kk][ty * 4];
            float4 a1 = *(const float4*)&As[kk][64 + ty * 4];
            float4 b0 = *(const float4*)&Bs[kk][tx * 4];
            float4 b1 = *(const float4*)&Bs[kk][64 + tx * 4];
            float ra[8] = {a0.x, a0.y, a0.z, a0.w, a1.x, a1.y, a1.z, a1.w};
            float rb[8] = {b0.x, b0.y, b0.z, b0.w, b1.x, b1.y, b1.z, b1.w};
#pragma unroll
            for (int i = 0; i < 8; i++)
#pragma unroll
                for (int j = 0; j < 8; j++)
                    acc[i][j] = fmaf(ra[i], rb[j], acc[i][j]);
        }
        __syncthreads();
    }

    const int bm = blockIdx.x * BM;
#pragma unroll
    for (int ih = 0; ih < 2; ih++) {
#pragma unroll
        for (int ii = 0; ii < 4; ii++) {
            int m = bm + ih * 64 + ty * 4 + ii;
            int ai = ih * 4 + ii;
#pragma unroll
            for (int jh = 0; jh < 2; jh++) {
                int n = bn + jh * 64 + tx * 4;
                float4 o;
                o.x = acc[ai][jh * 4 + 0];
                o.y = acc[ai][jh * 4 + 1];
                o.z = acc[ai][jh * 4 + 2];
                o.w = acc[ai][jh * 4 + 3];
                *(float4*)(Cg + (size_t)m * N + n) = o;
            }
        }
    }
}

// ---------------------------------------------------------------------------
// Launch
// ---------------------------------------------------------------------------
extern "C" void kernel_launch(void* const* d_in, const int* in_sizes, int n_in,
                              void* d_out, int out_size)
{
    const float* q    = (const float*)d_in[0];
    const float* k    = (const float*)d_in[1];
    const float* v    = (const float*)d_in[2];
    const float* Wq   = (const float*)d_in[3];
    const float* bq   = (const float*)d_in[4];
    const float* Wk   = (const float*)d_in[5];
    const float* bk   = (const float*)d_in[6];
    const float* Wv   = (const float*)d_in[7];
    const float* bv   = (const float*)d_in[8];
    const float* mask = (const float*)d_in[9];
    float* out = (float*)d_out;

    // 1) Projections: M = B*T = 16384, N = 512
    dim3 gp((B_ * T_) / BM, D_ / BN);
    proj_kernel<<<gp, NT>>>(q, Wq, bq, 0);
    proj_kernel<<<gp, NT>>>(k, Wk, bk, 1);
    proj_kernel<<<gp, NT>>>(v, Wv, bv, 2);

    // 2) Scores (scale + mask fused in epilogue)
    dim3 gs(T_ / BM, T_ / BN, B_);
    score_kernel<<<gs, NT>>>(mask);

    // 3) Row softmax
    softmax_kernel<<<B_ * T_, NT>>>();

    // 4) O = P @ V
    dim3 go(T_ / BM, D_ / BN, B_);
    pv_kernel<<<go, NT>>>(out);
}

// round 13
// speedup vs baseline: 1.8597x; 1.8557x over previous
#include <cuda_runtime.h>
#include <cuda_bf16.h>
#include <cstdint>
#include <cstddef>

#define B_  8
#define T_  2048
#define D_  512

#define BM  128
#define BN  128
#define BK  32
#define BKP 40      // padded k-stride (bf16 elems) = 80B rows -> conflict-free fragment LDS
#define NT  256

typedef __nv_bfloat16 BF;

// ---------------------------------------------------------------------------
// Scratch (__device__ globals: allocation-free rule)
// ---------------------------------------------------------------------------
__device__ BF g_QPh[B_*T_*D_], g_QPl[B_*T_*D_];
__device__ BF g_KPh[B_*T_*D_], g_KPl[B_*T_*D_];
__device__ BF g_VTh[B_*T_*D_], g_VTl[B_*T_*D_];            // V projected, [b][d][t]
__device__ float g_S[(size_t)B_*T_*T_];                    // masked scaled scores
__device__ BF g_Ph[(size_t)B_*T_*T_], g_Pl[(size_t)B_*T_*T_]; // softmax probs, split

// ---------------------------------------------------------------------------
// Helpers
// ---------------------------------------------------------------------------
__device__ __forceinline__ uint32_t pack2(BF a, BF b) {
    uint32_t u;
    asm("mov.b32 %0, {%1,%2};" : "=r"(u)
        : "h"(__bfloat16_as_ushort(a)), "h"(__bfloat16_as_ushort(b)));
    return u;
}

__device__ __forceinline__ void split1(float x, BF& h, BF& l) {
    h = __float2bfloat16_rn(x);
    l = __float2bfloat16_rn(x - __bfloat162float(h));
}

// store float4 as 4 hi-bf16 + 4 lo-bf16 (uint2 each)
__device__ __forceinline__ void store_split4(BF* ph, BF* pl, float4 v) {
    BF h0,l0,h1,l1,h2,l2,h3,l3;
    split1(v.x,h0,l0); split1(v.y,h1,l1); split1(v.z,h2,l2); split1(v.w,h3,l3);
    uint2 uh; uh.x = pack2(h0,h1); uh.y = pack2(h2,h3);
    uint2 ul; ul.x = pack2(l0,l1); ul.y = pack2(l2,l3);
    *(uint2*)ph = uh;
    *(uint2*)pl = ul;
}

__device__ __forceinline__ void mma_bf16(float4& d, const uint32_t* a, const uint32_t* b) {
    asm volatile(
        "mma.sync.aligned.m16n8k16.row.col.f32.bf16.bf16.f32 "
        "{%0,%1,%2,%3}, {%4,%5,%6,%7}, {%8,%9}, {%0,%1,%2,%3};\n"
        : "+f"(d.x), "+f"(d.y), "+f"(d.z), "+f"(d.w)
        : "r"(a[0]), "r"(a[1]), "r"(a[2]), "r"(a[3]), "r"(b[0]), "r"(b[1]));
}

// ---------------------------------------------------------------------------
// Shared mainloop step: consumes one BK=32 tile (As/Bs in [row][k] bf16, split).
// Computes hi*hi + hi*lo + lo*hi  (lo*lo dropped, ~2^-18).
// Warp tile 64x32: 4 m-tiles (16) x 4 n-tiles (8).
// ---------------------------------------------------------------------------
__device__ __forceinline__ void mma_step(
    const BF* __restrict__ Ah, const BF* __restrict__ Al,
    const BF* __restrict__ Bh, const BF* __restrict__ Bl,
    int mw, int nw, int g, int tg, float4 acc[4][4])
{
#pragma unroll
    for (int ks = 0; ks < BK; ks += 16) {
        uint32_t af[4][4], bh[4][2], bl[4][2];
#pragma unroll
        for (int mt = 0; mt < 4; mt++) {
            const BF* p = Ah + (mw + mt*16 + g) * BKP + ks + 2*tg;
            af[mt][0] = *(const uint32_t*)(p);
            af[mt][1] = *(const uint32_t*)(p + 8*BKP);
            af[mt][2] = *(const uint32_t*)(p + 8);
            af[mt][3] = *(const uint32_t*)(p + 8*BKP + 8);
        }
#pragma unroll
        for (int nt = 0; nt < 4; nt++) {
            const BF* p = Bh + (nw + nt*8 + g) * BKP + ks + 2*tg;
            bh[nt][0] = *(const uint32_t*)(p);
            bh[nt][1] = *(const uint32_t*)(p + 8);
            const BF* q = Bl + (nw + nt*8 + g) * BKP + ks + 2*tg;
            bl[nt][0] = *(const uint32_t*)(q);
            bl[nt][1] = *(const uint32_t*)(q + 8);
        }
#pragma unroll
        for (int mt = 0; mt < 4; mt++)
#pragma unroll
            for (int nt = 0; nt < 4; nt++)
                mma_bf16(acc[mt][nt], af[mt], bh[nt]);       // hi*hi
#pragma unroll
        for (int mt = 0; mt < 4; mt++)
#pragma unroll
            for (int nt = 0; nt < 4; nt++)
                mma_bf16(acc[mt][nt], af[mt], bl[nt]);       // hi*lo
#pragma unroll
        for (int mt = 0; mt < 4; mt++) {                     // reload A as lo
            const BF* p = Al + (mw + mt*16 + g) * BKP + ks + 2*tg;
            af[mt][0] = *(const uint32_t*)(p);
            af[mt][1] = *(const uint32_t*)(p + 8*BKP);
            af[mt][2] = *(const uint32_t*)(p + 8);
            af[mt][3] = *(const uint32_t*)(p + 8*BKP + 8);
        }
#pragma unroll
        for (int mt = 0; mt < 4; mt++)
#pragma unroll
            for (int nt = 0; nt < 4; nt++)
                mma_bf16(acc[mt][nt], af[mt], bh[nt]);       // lo*hi
    }
}

// ---------------------------------------------------------------------------
// Projection: C[m,n] = sum_k X[m,k]*W[n,k] + bias[n];  M=B*T, N=K=512.
// which: 0 -> QP split, 1 -> KP split, 2 -> VP split TRANSPOSED to [b][d][t]
// ---------------------------------------------------------------------------
__global__ __launch_bounds__(NT, 2) void proj_kernel(
    const float* __restrict__ X, const float* __restrict__ W,
    const float* __restrict__ bias, int which)
{
    const int K = D_, N = D_;
    __shared__ __align__(16) BF As_h[BM][BKP], As_l[BM][BKP];
    __shared__ __align__(16) BF Bs_h[BN][BKP], Bs_l[BN][BKP];

    const int tid = threadIdx.x;
    const int bm = blockIdx.x * BM, bn = blockIdx.y * BN;
    const int warp = tid >> 5, lane = tid & 31;
    const int mw = (warp & 1) * 64, nw = (warp >> 1) * 32;
    const int g = lane >> 2, tg = lane & 3;

    float4 acc[4][4];
#pragma unroll
    for (int i = 0; i < 4; i++)
#pragma unroll
        for (int j = 0; j < 4; j++) acc[i][j] = make_float4(0.f, 0.f, 0.f, 0.f);

    const float* Ag = X + (size_t)bm * K;
    const float* Bg = W + (size_t)bn * K;

    for (int k0 = 0; k0 < K; k0 += BK) {
#pragma unroll
        for (int i = 0; i < 4; i++) {
            int idx = tid + i * NT;
            int r = idx >> 3, c = (idx & 7) << 2;
            float4 a = *(const float4*)(Ag + (size_t)r * K + k0 + c);
            store_split4(&As_h[r][c], &As_l[r][c], a);
            float4 b = *(const float4*)(Bg + (size_t)r * K + k0 + c);
            store_split4(&Bs_h[r][c], &Bs_l[r][c], b);
        }
        __syncthreads();
        mma_step(&As_h[0][0], &As_l[0][0], &Bs_h[0][0], &Bs_l[0][0], mw, nw, g, tg, acc);
        __syncthreads();
    }

    BF* Ch = (which == 0) ? g_QPh : g_KPh;
    BF* Cl = (which == 0) ? g_QPl : g_KPl;

#pragma unroll
    for (int mt = 0; mt < 4; mt++)
#pragma unroll
        for (int nt = 0; nt < 4; nt++) {
            int m = bm + mw + mt * 16 + g;
            int n = bn + nw + nt * 8 + tg * 2;
            float2 bz = *(const float2*)(bias + n);
            float v0 = acc[mt][nt].x + bz.x, v1 = acc[mt][nt].y + bz.y;
            float v2 = acc[mt][nt].z + bz.x, v3 = acc[mt][nt].w + bz.y;
            BF h0,l0,h1,l1,h2,l2,h3,l3;
            split1(v0,h0,l0); split1(v1,h1,l1); split1(v2,h2,l2); split1(v3,h3,l3);
            if (which < 2) {
                *(uint32_t*)(Ch + (size_t)m * N + n)       = pack2(h0, h1);
                *(uint32_t*)(Cl + (size_t)m * N + n)       = pack2(l0, l1);
                *(uint32_t*)(Ch + (size_t)(m + 8) * N + n) = pack2(h2, h3);
                *(uint32_t*)(Cl + (size_t)(m + 8) * N + n) = pack2(l2, l3);
            } else {
                int b = m >> 11, t = m & (T_ - 1);
                size_t base = (size_t)b * D_ * T_;
                g_VTh[base + (size_t)n       * T_ + t]     = h0;
                g_VTl[base + (size_t)n       * T_ + t]     = l0;
                g_VTh[base + (size_t)(n + 1) * T_ + t]     = h1;
                g_VTl[base + (size_t)(n + 1) * T_ + t]     = l1;
                g_VTh[base + (size_t)n       * T_ + t + 8] = h2;
                g_VTl[base + (size_t)n       * T_ + t + 8] = l2;
                g_VTh[base + (size_t)(n + 1) * T_ + t + 8] = h3;
                g_VTl[base + (size_t)(n + 1) * T_ + t + 8] = l3;
            }
        }
}

// ---------------------------------------------------------------------------
// Scores: S[b,m,n] = (QP[b,m,:] . KP[b,n,:]) * scale * mask[b,m,n]
// ---------------------------------------------------------------------------
__global__ __launch_bounds__(NT, 2) void score_kernel(const float* __restrict__ mask)
{
    const int K = D_, N = T_;
    const float scale = 0.04419417382415922f;  // 1/sqrt(512)

    const int b = blockIdx.z;
    const BF* Agh = g_QPh + (size_t)b * T_ * D_ + (size_t)blockIdx.x * BM * K;
    const BF* Agl = g_QPl + (size_t)b * T_ * D_ + (size_t)blockIdx.x * BM * K;
    const BF* Bgh = g_KPh + (size_t)b * T_ * D_ + (size_t)blockIdx.y * BN * K;
    const BF* Bgl = g_KPl + (size_t)b * T_ * D_ + (size_t)blockIdx.y * BN * K;
    const float* Mg = mask + (size_t)b * T_ * T_;
    float*       Cg = g_S  + (size_t)b * T_ * T_;

    __shared__ __align__(16) BF As_h[BM][BKP], As_l[BM][BKP];
    __shared__ __align__(16) BF Bs_h[BN][BKP], Bs_l[BN][BKP];

    const int tid = threadIdx.x;
    const int warp = tid >> 5, lane = tid & 31;
    const int mw = (warp & 1) * 64, nw = (warp >> 1) * 32;
    const int g = lane >> 2, tg = lane & 3;

    float4 acc[4][4];
#pragma unroll
    for (int i = 0; i < 4; i++)
#pragma unroll
        for (int j = 0; j < 4; j++) acc[i][j] = make_float4(0.f, 0.f, 0.f, 0.f);

    for (int k0 = 0; k0 < K; k0 += BK) {
#pragma unroll
        for (int i = 0; i < 4; i++) {
            int idx = tid + i * NT;
            int r = idx >> 3, c = (idx & 7) << 2;
            *(uint2*)&As_h[r][c] = *(const uint2*)(Agh + (size_t)r * K + k0 + c);
            *(uint2*)&As_l[r][c] = *(const uint2*)(Agl + (size_t)r * K + k0 + c);
            *(uint2*)&Bs_h[r][c] = *(const uint2*)(Bgh + (size_t)r * K + k0 + c);
            *(uint2*)&Bs_l[r][c] = *(const uint2*)(Bgl + (size_t)r * K + k0 + c);
        }
        __syncthreads();
        mma_step(&As_h[0][0], &As_l[0][0], &Bs_h[0][0], &Bs_l[0][0], mw, nw, g, tg, acc);
        __syncthreads();
    }

    const int bm = blockIdx.x * BM, bn = blockIdx.y * BN;
#pragma unroll
    for (int mt = 0; mt < 4; mt++)
#pragma unroll
        for (int nt = 0; nt < 4; nt++) {
            int m = bm + mw + mt * 16 + g;
            int n = bn + nw + nt * 8 + tg * 2;
            float2 mk0 = *(const float2*)(Mg + (size_t)m * N + n);
            float2 mk1 = *(const float2*)(Mg + (size_t)(m + 8) * N + n);
            float2 o0, o1;
            o0.x = acc[mt][nt].x * scale * mk0.x;
            o0.y = acc[mt][nt].y * scale * mk0.y;
            o1.x = acc[mt][nt].z * scale * mk1.x;
            o1.y = acc[mt][nt].w * scale * mk1.y;
            *(float2*)(Cg + (size_t)m * N + n)       = o0;
            *(float2*)(Cg + (size_t)(m + 8) * N + n) = o1;
        }
}

// ---------------------------------------------------------------------------
// Row softmax over g_S; emits P pre-split (bf16 hi/lo). One CTA per row.
// ---------------------------------------------------------------------------
__global__ __launch_bounds__(NT) void softmax_kernel()
{
    const float* p = g_S + (size_t)blockIdx.x * T_;
    const int tid = threadIdx.x;

    float4 a = *(const float4*)(p + tid * 4);
    float4 b = *(const float4*)(p + 1024 + tid * 4);

    float m = fmaxf(fmaxf(fmaxf(a.x, a.y), fmaxf(a.z, a.w)),
                    fmaxf(fmaxf(b.x, b.y), fmaxf(b.z, b.w)));

    __shared__ float red[NT];
    red[tid] = m;
    __syncthreads();
#pragma unroll
    for (int s = NT / 2; s > 0; s >>= 1) {
        if (tid < s) red[tid] = fmaxf(red[tid], red[tid + s]);
        __syncthreads();
    }
    float rowmax = red[0];
    __syncthreads();

    a.x = __expf(a.x - rowmax); a.y = __expf(a.y - rowmax);
    a.z = __expf(a.z - rowmax); a.w = __expf(a.w - rowmax);
    b.x = __expf(b.x - rowmax); b.y = __expf(b.y - rowmax);
    b.z = __expf(b.z - rowmax); b.w = __expf(b.w - rowmax);

    float s8 = (a.x + a.y) + (a.z + a.w) + (b.x + b.y) + (b.z + b.w);
    red[tid] = s8;
    __syncthreads();
#pragma unroll
    for (int s = NT / 2; s > 0; s >>= 1) {
        if (tid < s) red[tid] += red[tid + s];
        __syncthreads();
    }
    float inv = 1.0f / red[0];

    a.x *= inv; a.y *= inv; a.z *= inv; a.w *= inv;
    b.x *= inv; b.y *= inv; b.z *= inv; b.w *= inv;

    size_t row = (size_t)blockIdx.x * T_;
    store_split4(g_Ph + row + tid * 4,        g_Pl + row + tid * 4,        a);
    store_split4(g_Ph + row + 1024 + tid * 4, g_Pl + row + 1024 + tid * 4, b);
}

// ---------------------------------------------------------------------------
// Output: O[b,m,n] = sum_k P[b,m,k] * VT[b,n,k]   (VT is [b][d][t], so NT form)
// ---------------------------------------------------------------------------
__global__ __launch_bounds__(NT, 2) void pv_kernel(float* __restrict__ out)
{
    const int K = T_, N = D_;

    const int b = blockIdx.z;
    const BF* Agh = g_Ph + (size_t)b * T_ * T_ + (size_t)blockIdx.x * BM * K;
    const BF* Agl = g_Pl + (size_t)b * T_ * T_ + (size_t)blockIdx.x * BM * K;
    const BF* Bgh = g_VTh + (size_t)b * D_ * T_ + (size_t)blockIdx.y * BN * K;
    const BF* Bgl = g_VTl + (size_t)b * D_ * T_ + (size_t)blockIdx.y * BN * K;
    float*    Cg  = out   + (size_t)b * T_ * D_;

    __shared__ __align__(16) BF As_h[BM][BKP], As_l[BM][BKP];
    __shared__ __align__(16) BF Bs_h[BN][BKP], Bs_l[BN][BKP];

    const int tid = threadIdx.x;
    const int warp = tid >> 5, lane = tid & 31;
    const int mw = (warp & 1) * 64, nw = (warp >> 1) * 32;
    const int g = lane >> 2, tg = lane & 3;

    float4 acc[4][4];
#pragma unroll
    for (int i = 0; i < 4; i++)
#pragma unroll
        for (int j = 0; j < 4; j++) acc[i][j] = make_float4(0.f, 0.f, 0.f, 0.f);

    for (int k0 = 0; k0 < K; k0 += BK) {
#pragma unroll
        for (int i = 0; i < 4; i++) {
            int idx = tid + i * NT;
            int r = idx >> 3, c = (idx & 7) << 2;
            *(uint2*)&As_h[r][c] = *(const uint2*)(Agh + (size_t)r * K + k0 + c);
            *(uint2*)&As_l[r][c] = *(const uint2*)(Agl + (size_t)r * K + k0 + c);
            *(uint2*)&Bs_h[r][c] = *(const uint2*)(Bgh + (size_t)r * K + k0 + c);
            *(uint2*)&Bs_l[r][c] = *(const uint2*)(Bgl + (size_t)r * K + k0 + c);
        }
        __syncthreads();
        mma_step(&As_h[0][0], &As_l[0][0], &Bs_h[0][0], &Bs_l[0][0], mw, nw, g, tg, acc);
        __syncthreads();
    }

    const int bm = blockIdx.x * BM, bn = blockIdx.y * BN;
#pragma unroll
    for (int mt = 0; mt < 4; mt++)
#pragma unroll
        for (int nt = 0; nt < 4; nt++) {
            int m = bm + mw + mt * 16 + g;
            int n = bn + nw + nt * 8 + tg * 2;
            float2 o0 = make_float2(acc[mt][nt].x, acc[mt][nt].y);
            float2 o1 = make_float2(acc[mt][nt].z, acc[mt][nt].w);
            *(float2*)(Cg + (size_t)m * N + n)       = o0;
            *(float2*)(Cg + (size_t)(m + 8) * N + n) = o1;
        }
}

// ---------------------------------------------------------------------------
// Launch
// ---------------------------------------------------------------------------
extern "C" void kernel_launch(void* const* d_in, const int* in_sizes, int n_in,
                              void* d_out, int out_size)
{
    const float* q    = (const float*)d_in[0];
    const float* k    = (const float*)d_in[1];
    const float* v    = (const float*)d_in[2];
    const float* Wq   = (const float*)d_in[3];
    const float* bq   = (const float*)d_in[4];
    const float* Wk   = (const float*)d_in[5];
    const float* bk   = (const float*)d_in[6];
    const float* Wv   = (const float*)d_in[7];
    const float* bv   = (const float*)d_in[8];
    const float* mask = (const float*)d_in[9];
    float* out = (float*)d_out;

    dim3 gp((B_ * T_) / BM, D_ / BN);
    proj_kernel<<<gp, NT>>>(q, Wq, bq, 0);
    proj_kernel<<<gp, NT>>>(k, Wk, bk, 1);
    proj_kernel<<<gp, NT>>>(v, Wv, bv, 2);

    dim3 gs(T_ / BM, T_ / BN, B_);
    score_kernel<<<gs, NT>>>(mask);

    softmax_kernel<<<B_ * T_, NT>>>();

    dim3 go(T_ / BM, D_ / BN, B_);
    pv_kernel<<<go, NT>>>(out);
}